// round 1
// baseline (speedup 1.0000x reference)
#include <cuda_runtime.h>
#include <stdint.h>

// MaxoutDynamic: per row of [nrows, 4096] fp32, zero the 2048 smallest values,
// scale survivors by 4096/2048 = 2.0. Exact rank selection with stable-sort
// tie semantics (among values equal to the threshold, the LARGEST indices
// survive, matching jnp.argsort-based dropping of earliest-index ties).

#define FEAT    4096
#define KEEP    2048u
#define THREADS 256
#define EPT     16          // elements per thread
#define NWARP   (THREADS / 32)

// Monotonic float->uint key map (ascending float order == ascending uint order).
__device__ __forceinline__ unsigned f2key(unsigned b) {
    // negative: flip all bits; non-negative: flip sign bit
    return b ^ (((unsigned)((int)b >> 31)) | 0x80000000u);
}

// Block-wide count of (key[i] >= pivot). Two __syncthreads per call.
__device__ __forceinline__ unsigned bcount_ge(const unsigned (&key)[EPT], unsigned pivot,
                                              unsigned* scnt, int lane, int warp) {
    unsigned c = 0;
#pragma unroll
    for (int i = 0; i < EPT; ++i) c += (key[i] >= pivot) ? 1u : 0u;
#pragma unroll
    for (int o = 16; o; o >>= 1) c += __shfl_xor_sync(0xFFFFFFFFu, c, o);
    if (lane == 0) scnt[warp] = c;
    __syncthreads();
    unsigned t = 0;
#pragma unroll
    for (int w = 0; w < NWARP; ++w) t += scnt[w];
    __syncthreads();
    return t;
}

// Block-wide count of (key[i] == T && global_index >= c).
__device__ __forceinline__ unsigned bcount_eq_idx(const unsigned (&key)[EPT], unsigned T,
                                                  unsigned c, int tid,
                                                  unsigned* scnt, int lane, int warp) {
    unsigned cnt = 0;
#pragma unroll
    for (int i = 0; i < EPT; ++i) {
        unsigned idx = 4u * (unsigned)tid + 1024u * (unsigned)(i >> 2) + (unsigned)(i & 3);
        cnt += (key[i] == T && idx >= c) ? 1u : 0u;
    }
#pragma unroll
    for (int o = 16; o; o >>= 1) cnt += __shfl_xor_sync(0xFFFFFFFFu, cnt, o);
    if (lane == 0) scnt[warp] = cnt;
    __syncthreads();
    unsigned t = 0;
#pragma unroll
    for (int w = 0; w < NWARP; ++w) t += scnt[w];
    __syncthreads();
    return t;
}

__device__ __forceinline__ float outval(unsigned k, unsigned T, unsigned cutoff, unsigned idx) {
    bool keep = (k > T) || (k == T && idx >= cutoff);
    unsigned mask = 0x80000000u | ~((unsigned)((int)k >> 31));
    float v = __uint_as_float(k ^ mask);
    return keep ? v * 2.0f : 0.0f;
}

__global__ __launch_bounds__(THREADS)
void maxout_sel_kernel(const float* __restrict__ in, float* __restrict__ out, int nrows) {
    const int row = blockIdx.x;
    if (row >= nrows) return;
    const int tid  = threadIdx.x;
    const int lane = tid & 31;
    const int warp = tid >> 5;

    const uint4* in4  = reinterpret_cast<const uint4*>(in)  + (size_t)row * (FEAT / 4);
    float4*      out4 = reinterpret_cast<float4*>(out)      + (size_t)row * (FEAT / 4);

    // Load row as monotonic uint keys, 4x uint4 per thread, coalesced.
    unsigned key[EPT];
#pragma unroll
    for (int j = 0; j < 4; ++j) {
        uint4 u = in4[tid + THREADS * j];
        key[4 * j + 0] = f2key(u.x);
        key[4 * j + 1] = f2key(u.y);
        key[4 * j + 2] = f2key(u.z);
        key[4 * j + 3] = f2key(u.w);
    }

    __shared__ unsigned scnt[NWARP];

    // Binary search for T = 2048th-largest key:
    // T = max{v : count(key >= v) >= KEEP}. Invariant: f(lo) >= KEEP.
    unsigned lo = 0u, hi = 0xFFFFFFFFu;
    while (lo < hi) {
        unsigned d   = hi - lo;
        unsigned mid = lo + (d >> 1) + (d & 1u);   // upper mid, overflow-safe
        unsigned cnt = bcount_ge(key, mid, scnt, lane, warp);
        if (cnt >= KEEP) lo = mid; else hi = mid - 1u;
    }
    const unsigned T = lo;

    // Tie resolution: among keys == T, keep the kk = KEEP - count(>T) largest indices.
    unsigned cGT = (T == 0xFFFFFFFFu) ? 0u : bcount_ge(key, T + 1u, scnt, lane, warp);
    unsigned kk  = KEEP - cGT;
    unsigned cGE = bcount_ge(key, T, scnt, lane, warp);
    unsigned E   = cGE - cGT;

    unsigned cutoff = 0u;
    if (E != kk) {
        // cutoff = max{c : count(key==T && idx>=c) >= kk}; then exactly kk equals kept.
        unsigned clo = 0u, chi = FEAT - 1u;
        while (clo < chi) {
            unsigned d  = chi - clo;
            unsigned cm = clo + (d >> 1) + (d & 1u);
            unsigned c  = bcount_eq_idx(key, T, cm, tid, scnt, lane, warp);
            if (c >= kk) clo = cm; else chi = cm - 1u;
        }
        cutoff = clo;
    }

    // Write output: kept -> value * 2.0f, dropped -> 0. Coalesced float4 stores.
#pragma unroll
    for (int j = 0; j < 4; ++j) {
        unsigned ib = 4u * (unsigned)tid + 1024u * (unsigned)j;
        float4 o;
        o.x = outval(key[4 * j + 0], T, cutoff, ib + 0u);
        o.y = outval(key[4 * j + 1], T, cutoff, ib + 1u);
        o.z = outval(key[4 * j + 2], T, cutoff, ib + 2u);
        o.w = outval(key[4 * j + 3], T, cutoff, ib + 3u);
        out4[tid + THREADS * j] = o;
    }
}

extern "C" void kernel_launch(void* const* d_in, const int* in_sizes, int n_in,
                              void* d_out, int out_size) {
    const float* feat = (const float*)d_in[0];
    float* out = (float*)d_out;
    int nrows = in_sizes[0] / FEAT;
    maxout_sel_kernel<<<nrows, THREADS>>>(feat, out, nrows);
}

// round 2
// speedup vs baseline: 2.4380x; 2.4380x over previous
#include <cuda_runtime.h>
#include <stdint.h>

// MaxoutDynamic: per row of [nrows, 4096] fp32, zero the 2048 smallest values,
// scale survivors by 4096/2048 = 2.0. Exact rank selection.
//
// Algorithm: row in registers (16 keys/thread, 256 threads), bisection over
// monotonic uint32 key space with EARLY EXIT: if count(key >= mid) == 2048
// exactly, the kept set is {key >= mid} with no ambiguity (all excluded
// elements are strictly smaller), so we stop immediately. For Gaussian rows
// this fires around round 13-16 instead of running all 32 rounds.
// Fallback (ties straddling the boundary): finish bisection to lo==hi and
// resolve ties by index (stable-argsort semantics: largest indices survive).

#define FEAT    4096
#define KEEP    2048u
#define THREADS 256
#define EPT     16
#define NWARP   (THREADS / 32)

__device__ __forceinline__ unsigned f2key(unsigned b) {
    return b ^ (((unsigned)((int)b >> 31)) | 0x80000000u);
}

// Block-wide count of pred-sum c (each thread passes its local count).
// One REDUX.SUM per warp, per-warp partials combined via two LDS.128 loads.
__device__ __forceinline__ unsigned block_sum(unsigned c, unsigned* scnt,
                                              int lane, int warp) {
    c = __reduce_add_sync(0xFFFFFFFFu, c);
    if (lane == 0) scnt[warp] = c;
    __syncthreads();
    uint4 a = *reinterpret_cast<const uint4*>(scnt);
    uint4 b = *reinterpret_cast<const uint4*>(scnt + 4);
    unsigned t = a.x + a.y + a.z + a.w + b.x + b.y + b.z + b.w;
    __syncthreads();
    return t;
}

__device__ __forceinline__ unsigned cnt_ge(const unsigned (&key)[EPT], unsigned pivot) {
    unsigned c = 0;
#pragma unroll
    for (int i = 0; i < EPT; ++i) c += (key[i] >= pivot) ? 1u : 0u;
    return c;
}

__device__ __forceinline__ float outval(unsigned k, unsigned T, unsigned cutoff, unsigned idx) {
    bool keep = (k > T) || (k == T && idx >= cutoff);
    unsigned mask = 0x80000000u | ~((unsigned)((int)k >> 31));
    float v = __uint_as_float(k ^ mask);
    return keep ? v * 2.0f : 0.0f;
}

__global__ __launch_bounds__(THREADS)
void maxout_sel_kernel(const float* __restrict__ in, float* __restrict__ out) {
    const int row  = blockIdx.x;
    const int tid  = threadIdx.x;
    const int lane = tid & 31;
    const int warp = tid >> 5;

    const uint4* in4  = reinterpret_cast<const uint4*>(in)  + (size_t)row * (FEAT / 4);
    float4*      out4 = reinterpret_cast<float4*>(out)      + (size_t)row * (FEAT / 4);

    unsigned key[EPT];
#pragma unroll
    for (int j = 0; j < 4; ++j) {
        uint4 u = in4[tid + THREADS * j];
        key[4 * j + 0] = f2key(u.x);
        key[4 * j + 1] = f2key(u.y);
        key[4 * j + 2] = f2key(u.z);
        key[4 * j + 3] = f2key(u.w);
    }

    __shared__ unsigned scnt[NWARP];

    // Bisection for T = 2048th-largest key, with exact-count early exit.
    unsigned lo = 0u, hi = 0xFFFFFFFFu;
    unsigned T = 0u, cutoff = 0u;
    bool resolved = false;

    while (lo < hi) {
        unsigned d   = hi - lo;
        unsigned mid = lo + (d >> 1) + (d & 1u);   // upper mid, overflow-safe
        unsigned cnt = block_sum(cnt_ge(key, mid), scnt, lane, warp);
        if (cnt == KEEP) {            // exact split: kept set = {key >= mid}
            T = mid;                  // keep rule: key > T-?  -> (k>T)||(k==T&&idx>=0)
            cutoff = 0u;              //   == key >= mid, since T = mid, cutoff = 0
            resolved = true;
            break;
        }
        if (cnt > KEEP) lo = mid; else hi = mid - 1u;
    }

    if (!resolved) {
        // lo == hi == T; ties at T straddle the boundary. Keep the
        // kk = KEEP - count(>T) largest-index elements among those == T.
        T = lo;
        unsigned cGT = (T == 0xFFFFFFFFu) ? 0u
                     : block_sum(cnt_ge(key, T + 1u), scnt, lane, warp);
        unsigned kk  = KEEP - cGT;
        unsigned cGE = block_sum(cnt_ge(key, T), scnt, lane, warp);
        unsigned E   = cGE - cGT;

        if (E != kk) {
            // cutoff = max{c : count(key==T && idx>=c) >= kk}
            unsigned clo = 0u, chi = FEAT - 1u;
            while (clo < chi) {
                unsigned d  = chi - clo;
                unsigned cm = clo + (d >> 1) + (d & 1u);
                unsigned c  = 0;
#pragma unroll
                for (int i = 0; i < EPT; ++i) {
                    unsigned idx = 4u * (unsigned)tid + 1024u * (unsigned)(i >> 2) + (unsigned)(i & 3);
                    c += (key[i] == T && idx >= cm) ? 1u : 0u;
                }
                c = block_sum(c, scnt, lane, warp);
                if (c >= kk) clo = cm; else chi = cm - 1u;
            }
            cutoff = clo;
        }
    }

    // Write output: kept -> value * 2.0f, dropped -> 0.
#pragma unroll
    for (int j = 0; j < 4; ++j) {
        unsigned ib = 4u * (unsigned)tid + 1024u * (unsigned)j;
        float4 o;
        o.x = outval(key[4 * j + 0], T, cutoff, ib + 0u);
        o.y = outval(key[4 * j + 1], T, cutoff, ib + 1u);
        o.z = outval(key[4 * j + 2], T, cutoff, ib + 2u);
        o.w = outval(key[4 * j + 3], T, cutoff, ib + 3u);
        out4[tid + THREADS * j] = o;
    }
}

extern "C" void kernel_launch(void* const* d_in, const int* in_sizes, int n_in,
                              void* d_out, int out_size) {
    const float* feat = (const float*)d_in[0];
    float* out = (float*)d_out;
    int nrows = in_sizes[0] / FEAT;
    maxout_sel_kernel<<<nrows, THREADS>>>(feat, out);
}

// round 3
// speedup vs baseline: 2.9109x; 1.1939x over previous
#include <cuda_runtime.h>
#include <stdint.h>

// MaxoutDynamic: per row of [nrows, 4096] fp32, zero the 2048 smallest values,
// scale survivors by 4096/2048 = 2.0. Exact rank selection (= row median, since
// KEEP = FEAT/2), stable-argsort tie semantics (largest indices survive).
//
// Selection: row in registers (16 keys/thread, 256 thr), INTERPOLATION search
// over the monotone key<->value mapping:
//   - 2 fixed seed pivots at +-0.0822 (+-4.2 sigma of the sample-median dist)
//   - secant iterations on (value, count) bracket ends, clamped inside bracket
//   - early exit the moment count(key >= pivot) == KEEP (unambiguous split)
//   - key-space bisection fallback after 8 rounds (guaranteed termination)

#define FEAT    4096
#define KEEP    2048u
#define THREADS 256
#define EPT     16
#define NWARP   (THREADS / 32)

__device__ __forceinline__ unsigned f2key(unsigned b) {
    return b ^ (((unsigned)((int)b >> 31)) | 0x80000000u);
}
__device__ __forceinline__ float key2f(unsigned k) {
    unsigned b = (k & 0x80000000u) ? (k ^ 0x80000000u) : ~k;
    return __uint_as_float(b);
}

// Block-wide sum of per-thread counts: REDUX.SUM per warp, partials via LDS.128.
__device__ __forceinline__ unsigned block_sum(unsigned c, unsigned* scnt,
                                              int lane, int warp) {
    c = __reduce_add_sync(0xFFFFFFFFu, c);
    if (lane == 0) scnt[warp] = c;
    __syncthreads();
    uint4 a = *reinterpret_cast<const uint4*>(scnt);
    uint4 b = *reinterpret_cast<const uint4*>(scnt + 4);
    unsigned t = a.x + a.y + a.z + a.w + b.x + b.y + b.z + b.w;
    __syncthreads();
    return t;
}

__device__ __forceinline__ unsigned cnt_ge(const unsigned (&key)[EPT], unsigned pivot) {
    unsigned c = 0;
#pragma unroll
    for (int i = 0; i < EPT; ++i) c += (key[i] >= pivot) ? 1u : 0u;
    return c;
}

__device__ __forceinline__ float outval(unsigned k, unsigned T, unsigned cutoff, unsigned idx) {
    bool keep = (k > T) || (k == T && idx >= cutoff);
    unsigned mask = 0x80000000u | ~((unsigned)((int)k >> 31));
    float v = __uint_as_float(k ^ mask);
    return keep ? v * 2.0f : 0.0f;
}

__global__ __launch_bounds__(THREADS)
void maxout_sel_kernel(const float* __restrict__ in, float* __restrict__ out) {
    const int row  = blockIdx.x;
    const int tid  = threadIdx.x;
    const int lane = tid & 31;
    const int warp = tid >> 5;

    const uint4* in4  = reinterpret_cast<const uint4*>(in)  + (size_t)row * (FEAT / 4);
    float4*      out4 = reinterpret_cast<float4*>(out)      + (size_t)row * (FEAT / 4);

    unsigned key[EPT];
#pragma unroll
    for (int j = 0; j < 4; ++j) {
        uint4 u = in4[tid + THREADS * j];
        key[4 * j + 0] = f2key(u.x);
        key[4 * j + 1] = f2key(u.y);
        key[4 * j + 2] = f2key(u.z);
        key[4 * j + 3] = f2key(u.w);
    }

    __shared__ __align__(16) unsigned scnt[NWARP];

    // Bracket in key space (64-bit ends so the empty sentinel 2^32 is exact):
    //   cnt_ge(klo) >= KEEP   (klo = 0: all 4096 keys >= 0, trivially true)
    //   cnt_ge(khi) <  KEEP   (khi = 2^32: zero keys, vacuously true)
    unsigned long long klo = 0ULL, khi = 0x100000000ULL;
    unsigned c_klo = FEAT, c_khi = 0u;
    unsigned T = 0u, cutoff = 0u;
    bool resolved = false;

    int iter = 0;
    while (khi - klo > 1ULL) {
        unsigned pivot;
        if (iter == 0) {
            pivot = f2key(__float_as_uint(-0.0822f));
        } else if (iter == 1) {
            pivot = f2key(__float_as_uint(0.0822f));
        } else if (iter < 8 && klo != 0ULL && khi != 0x100000000ULL) {
            // Secant on bracket ends in float-value space.
            float vlo = key2f((unsigned)klo);
            float vhi = key2f((unsigned)khi);
            float fr  = ((float)c_klo - (float)KEEP) / ((float)c_klo - (float)c_khi);
            pivot = f2key(__float_as_uint(vlo + (vhi - vlo) * fr));
        } else {
            pivot = (unsigned)((klo + khi) >> 1);   // bisection fallback
        }
        // Clamp strictly inside the bracket so progress is guaranteed.
        if ((unsigned long long)pivot <= klo) pivot = (unsigned)(klo + 1ULL);
        if ((unsigned long long)pivot >= khi) pivot = (unsigned)(khi - 1ULL);

        unsigned c = block_sum(cnt_ge(key, pivot), scnt, lane, warp);
        if (c == KEEP) {          // exact split: kept set = {key >= pivot}
            T = pivot; cutoff = 0u; resolved = true; break;
        }
        if (c > KEEP) { klo = pivot; c_klo = c; }
        else          { khi = pivot; c_khi = c; }
        ++iter;
    }

    if (!resolved) {
        // khi == klo + 1:  T = klo,  cGE = c_klo,  cGT = c_khi  (no extra rounds).
        T = (unsigned)klo;
        unsigned kk = KEEP - c_khi;          // equals to keep among key == T
        // (c_klo - c_khi) > kk always here, so resolve ties by index:
        // cutoff = max{c : count(key==T && idx>=c) >= kk}
        unsigned clo = 0u, chi = FEAT - 1u;
        while (clo < chi) {
            unsigned d  = chi - clo;
            unsigned cm = clo + (d >> 1) + (d & 1u);
            unsigned c  = 0;
#pragma unroll
            for (int i = 0; i < EPT; ++i) {
                unsigned idx = 4u * (unsigned)tid + 1024u * (unsigned)(i >> 2) + (unsigned)(i & 3);
                c += (key[i] == T && idx >= cm) ? 1u : 0u;
            }
            c = block_sum(c, scnt, lane, warp);
            if (c >= kk) clo = cm; else chi = cm - 1u;
        }
        cutoff = clo;
    }

    // Write: kept -> value * 2.0f, dropped -> 0. Coalesced float4 stores.
#pragma unroll
    for (int j = 0; j < 4; ++j) {
        unsigned ib = 4u * (unsigned)tid + 1024u * (unsigned)j;
        float4 o;
        o.x = outval(key[4 * j + 0], T, cutoff, ib + 0u);
        o.y = outval(key[4 * j + 1], T, cutoff, ib + 1u);
        o.z = outval(key[4 * j + 2], T, cutoff, ib + 2u);
        o.w = outval(key[4 * j + 3], T, cutoff, ib + 3u);
        out4[tid + THREADS * j] = o;
    }
}

extern "C" void kernel_launch(void* const* d_in, const int* in_sizes, int n_in,
                              void* d_out, int out_size) {
    const float* feat = (const float*)d_in[0];
    float* out = (float*)d_out;
    int nrows = in_sizes[0] / FEAT;
    maxout_sel_kernel<<<nrows, THREADS>>>(feat, out);
}

// round 4
// speedup vs baseline: 3.9782x; 1.3666x over previous
#include <cuda_runtime.h>
#include <stdint.h>

// MaxoutDynamic: per row of [nrows, 4096] fp32, zero the 2048 smallest values,
// scale survivors by 4096/2048 = 2.0. Exact rank selection (row median).
//
// Float-domain selection: 16 floats/thread in registers. Two seed pivots
// (+-0.0822 = +-4.2 sigma of the sample-median distribution) counted DURING
// the load (packed, one reduction). Then secant iterations on the (value,
// count) bracket with early exit when count == 2048 exactly (unambiguous
// split); key-space bisection fallback guarantees termination. Ties resolved
// by index (stable-argsort semantics: largest indices survive; float equality
// groups +-0.0 exactly like the reference).

#define FEAT    4096
#define KEEP    2048u
#define THREADS 256
#define EPT     16
#define NWARP   (THREADS / 32)
#define SEED    0.0822f

__device__ __forceinline__ unsigned f2key(unsigned b) {
    return b ^ (((unsigned)((int)b >> 31)) | 0x80000000u);
}
__device__ __forceinline__ float key2f(unsigned k) {
    unsigned b = (k & 0x80000000u) ? (k ^ 0x80000000u) : ~k;
    return __uint_as_float(b);
}

// Block sum; caller alternates buf between the two halves of scnt (ping-pong)
// so only ONE __syncthreads per call is needed.
__device__ __forceinline__ unsigned block_sum(unsigned c, unsigned* buf,
                                              int lane, int warp) {
    c = __reduce_add_sync(0xFFFFFFFFu, c);
    if (lane == 0) buf[warp] = c;
    __syncthreads();
    uint4 a = *reinterpret_cast<const uint4*>(buf);
    uint4 b = *reinterpret_cast<const uint4*>(buf + 4);
    return a.x + a.y + a.z + a.w + b.x + b.y + b.z + b.w;
}

__global__ __launch_bounds__(THREADS)
void maxout_sel_kernel(const float* __restrict__ in, float* __restrict__ out) {
    const int row  = blockIdx.x;
    const int tid  = threadIdx.x;
    const int lane = tid & 31;
    const int warp = tid >> 5;

    const float4* in4  = reinterpret_cast<const float4*>(in)  + (size_t)row * (FEAT / 4);
    float4*       out4 = reinterpret_cast<float4*>(out)       + (size_t)row * (FEAT / 4);

    __shared__ __align__(16) unsigned scnt[2][NWARP];
    int par = 0;

    // Load row + count both seed pivots in the same pass (overlaps LDG latency).
    float v[EPT];
    unsigned c1 = 0, c2 = 0;   // c1 = #{v >= -SEED}, c2 = #{v >= +SEED}
#pragma unroll
    for (int j = 0; j < 4; ++j) {
        float4 u = in4[tid + THREADS * j];
        v[4 * j + 0] = u.x; v[4 * j + 1] = u.y;
        v[4 * j + 2] = u.z; v[4 * j + 3] = u.w;
#pragma unroll
        for (int i = 0; i < 4; ++i) {
            float x = v[4 * j + i];
            c1 += (x >= -SEED) ? 1u : 0u;
            c2 += (x >=  SEED) ? 1u : 0u;
        }
    }
    {   // one packed reduction for both seed counts (each block total <= 4096)
        unsigned packed = block_sum((c1 << 13) | c2, scnt[par], lane, warp);
        par ^= 1;
        c1 = packed >> 13;
        c2 = packed & 0x1FFFu;
    }

    float T = 0.0f;
    unsigned cutoff = 0u;
    bool resolved = false;

    // Bracket state: keys for exact termination, floats for secant.
    unsigned long long klo, khi;
    float vlo = 0.f, vhi = 0.f;
    unsigned c_klo, c_khi;

    if (c1 == KEEP)      { T = -SEED; resolved = true; }
    else if (c2 == KEEP) { T =  SEED; resolved = true; }
    else if (c1 < KEEP)  {           // median below -SEED
        klo = 0ULL;                      c_klo = FEAT;
        khi = f2key(__float_as_uint(-SEED)); c_khi = c1; vhi = -SEED;
    } else if (c2 > KEEP) {          // median above +SEED
        klo = f2key(__float_as_uint(SEED)); c_klo = c2; vlo = SEED;
        khi = 0x100000000ULL;            c_khi = 0u;
    } else {                          // median inside [-SEED, SEED]
        klo = f2key(__float_as_uint(-SEED)); c_klo = c1; vlo = -SEED;
        khi = f2key(__float_as_uint( SEED)); c_khi = c2; vhi =  SEED;
    }

    int iter = 0;
    while (!resolved && khi - klo > 1ULL) {
        unsigned pk;
        if (iter < 8 && klo != 0ULL && khi != 0x100000000ULL) {
            // Secant in value space on the bracket ends.
            float fr = ((float)c_klo - (float)KEEP) / ((float)c_klo - (float)c_khi);
            pk = f2key(__float_as_uint(vlo + (vhi - vlo) * fr));
        } else {
            pk = (unsigned)((klo + khi) >> 1);
        }
        if ((unsigned long long)pk <= klo) pk = (unsigned)(klo + 1ULL);
        if ((unsigned long long)pk >= khi) pk = (unsigned)(khi - 1ULL);
        float p = key2f(pk);

        unsigned c = 0;
#pragma unroll
        for (int i = 0; i < EPT; ++i) c += (v[i] >= p) ? 1u : 0u;
        c = block_sum(c, scnt[par], lane, warp);
        par ^= 1;

        if (c == KEEP) { T = p; resolved = true; break; }
        if (c > KEEP) { klo = pk; c_klo = c; vlo = p; }
        else          { khi = pk; c_khi = c; vhi = p; }
        ++iter;
    }

    if (!resolved) {
        // khi == klo + 1; klo was probed, so c_klo = #{v >= T} with T below.
        T = key2f((unsigned)klo);
        // Strict-greater count (float semantics, handles +-0 tie class).
        unsigned cGT = 0;
#pragma unroll
        for (int i = 0; i < EPT; ++i) cGT += (v[i] > T) ? 1u : 0u;
        cGT = block_sum(cGT, scnt[par], lane, warp);
        par ^= 1;

        unsigned kk = KEEP - cGT;          // equals to keep
        unsigned E  = c_klo - cGT;         // size of equality class
        if (E != kk) {
            // cutoff = max{c : #{v == T && idx >= c} >= kk}
            unsigned clo = 0u, chi = FEAT - 1u;
            while (clo < chi) {
                unsigned d  = chi - clo;
                unsigned cm = clo + (d >> 1) + (d & 1u);
                unsigned c  = 0;
#pragma unroll
                for (int i = 0; i < EPT; ++i) {
                    unsigned idx = 4u * (unsigned)tid + 1024u * (unsigned)(i >> 2) + (unsigned)(i & 3);
                    c += (v[i] == T && idx >= cm) ? 1u : 0u;
                }
                c = block_sum(c, scnt[par], lane, warp);
                par ^= 1;
                if (c >= kk) clo = cm; else chi = cm - 1u;
            }
            cutoff = clo;
        }
    }

    // Output. cutoff is uniform across the block, so this branch is uniform.
    if (cutoff == 0u) {
#pragma unroll
        for (int j = 0; j < 4; ++j) {
            float4 o;
            o.x = (v[4 * j + 0] >= T) ? v[4 * j + 0] * 2.0f : 0.0f;
            o.y = (v[4 * j + 1] >= T) ? v[4 * j + 1] * 2.0f : 0.0f;
            o.z = (v[4 * j + 2] >= T) ? v[4 * j + 2] * 2.0f : 0.0f;
            o.w = (v[4 * j + 3] >= T) ? v[4 * j + 3] * 2.0f : 0.0f;
            out4[tid + THREADS * j] = o;
        }
    } else {
#pragma unroll
        for (int j = 0; j < 4; ++j) {
            unsigned ib = 4u * (unsigned)tid + 1024u * (unsigned)j;
            float4 o;
            float* po = &o.x;
#pragma unroll
            for (int i = 0; i < 4; ++i) {
                float x = v[4 * j + i];
                bool keep = (x > T) || (x == T && (ib + i) >= cutoff);
                po[i] = keep ? x * 2.0f : 0.0f;
            }
            out4[tid + THREADS * j] = o;
        }
    }
}

extern "C" void kernel_launch(void* const* d_in, const int* in_sizes, int n_in,
                              void* d_out, int out_size) {
    const float* feat = (const float*)d_in[0];
    float* out = (float*)d_out;
    int nrows = in_sizes[0] / FEAT;
    maxout_sel_kernel<<<nrows, THREADS>>>(feat, out);
}